// round 14
// baseline (speedup 1.0000x reference)
#include <cuda_runtime.h>
#include <cuda_fp16.h>
#include <math.h>
#include <stdint.h>

#define CB 256
#define CL 256
#define CS 253
#define CD 768
#define CH 128
#define ROWCAP (CB * CL + 256)

// ---- scratch (static device globals; zero-initialized at module load) ----
__device__ __align__(256) __half g_MT[CD * CD];                   // (s*WQ@WK^T)^T, n-major
__device__ __align__(256) __half g_ctx_c[(size_t)ROWCAP * CD];    // compacted ctx rows
__device__ __align__(256) __half g_qc[(size_t)ROWCAP * CD];       // compacted q'' rows
__device__ __align__(256) __half g_cand_c[(size_t)CB * 256 * CD]; // per-batch compacted cand
__device__ float g_v[CB * 256];   // v' at compacted col positions (0 on pads)
__device__ float g_x[CB * CL];
__device__ int g_rowmap[ROWCAP];
__device__ int g_colmap[CB * 256];
__device__ int g_start[CB];
__device__ int g_cnt[CB];
__device__ int g_cnt_s[CB];
__device__ int g_total;

// =====================================================================
// helpers
// =====================================================================
__device__ __forceinline__ unsigned f2tf(float f) {
  unsigned r;
  asm("cvt.rna.tf32.f32 %0, %1;" : "=r"(r) : "f"(f));
  return r;
}

__device__ __forceinline__ uint32_t smem_u32(const void* p) {
  uint32_t a;
  asm("{ .reg .u64 t; cvta.to.shared.u64 t, %1; cvt.u32.u64 %0, t; }" : "=r"(a) : "l"(p));
  return a;
}

__device__ __forceinline__ void cp16(uint32_t dst, const void* src) {
  asm volatile("cp.async.cg.shared.global [%0], [%1], 16;" ::"r"(dst), "l"(src) : "memory");
}
#define CP_COMMIT() asm volatile("cp.async.commit_group;" ::: "memory")
// 3-stage pipeline, prologue commits 2 groups, loop issues kt+2:
// wait until <=1 pending so stage kt is complete (R5 lesson: NOT 2).
#define CP_WAIT1() asm volatile("cp.async.wait_group 1;" ::: "memory")

// legacy tf32 mma for the tiny K0 (fp32 inputs)
__device__ __forceinline__ void mma8(float c[4], const unsigned a[4],
                                     unsigned b0, unsigned b1) {
  asm volatile(
      "mma.sync.aligned.m16n8k8.row.col.f32.tf32.tf32.f32 "
      "{%0,%1,%2,%3}, {%4,%5,%6,%7}, {%8,%9}, {%0,%1,%2,%3};"
      : "+f"(c[0]), "+f"(c[1]), "+f"(c[2]), "+f"(c[3])
      : "r"(a[0]), "r"(a[1]), "r"(a[2]), "r"(a[3]), "r"(b0), "r"(b1));
}

// fp16 mma, fp32 accumulate
__device__ __forceinline__ void mma16(float c[4], const unsigned a[4],
                                      unsigned b0, unsigned b1) {
  asm volatile(
      "mma.sync.aligned.m16n8k16.row.col.f32.f16.f16.f32 "
      "{%0,%1,%2,%3}, {%4,%5,%6,%7}, {%8,%9}, {%0,%1,%2,%3};"
      : "+f"(c[0]), "+f"(c[1]), "+f"(c[2]), "+f"(c[3])
      : "r"(a[0]), "r"(a[1]), "r"(a[2]), "r"(a[3]), "r"(b0), "r"(b1));
}

#define LDSM_X4(r0, r1, r2, r3, addr)                                          \
  asm volatile("ldmatrix.sync.aligned.m8n8.x4.shared.b16 {%0,%1,%2,%3}, [%4];" \
               : "=r"(r0), "=r"(r1), "=r"(r2), "=r"(r3)                        \
               : "r"(addr))

__device__ __forceinline__ uint32_t pack2h(float a, float b) {
  __half2 h = __floats2half2_rn(a, b);
  return *(uint32_t*)&h;
}

// =====================================================================
// scan1: per-batch mask counts + prefix (parallel, R12-proven).
// =====================================================================
__global__ void __launch_bounds__(1024) scan1(const int* __restrict__ ctx_mask,
                                              const int* __restrict__ cand_mask) {
  __shared__ int sc[CB];
  __shared__ int cnts[CB];
  const int t = threadIdx.x;
  const int b = t >> 2, q = t & 3;

  const int4* cm4 = (const int4*)ctx_mask + b * 64 + q * 16;
  int s = 0;
#pragma unroll
  for (int i = 0; i < 16; i++) {
    int4 v = cm4[i];
    s += v.x + v.y + v.z + v.w;
  }
  s += __shfl_xor_sync(~0u, s, 1);
  s += __shfl_xor_sync(~0u, s, 2);

  const int* smk = cand_mask + b * CS + q * 64;
  const int e = (q == 3) ? (CS - 192) : 64;
  int s2 = 0;
#pragma unroll 8
  for (int i = 0; i < e; i++) s2 += smk[i];
  s2 += __shfl_xor_sync(~0u, s2, 1);
  s2 += __shfl_xor_sync(~0u, s2, 2);

  if (q == 0) {
    g_cnt[b] = s;
    g_cnt_s[b] = s2;
    sc[b] = s;
    cnts[b] = s;
  }
  __syncthreads();
  for (int off = 1; off < CB; off <<= 1) {
    int v = 0;
    if (t < CB && t >= off) v = sc[t - off];
    __syncthreads();
    if (t < CB) sc[t] += v;
    __syncthreads();
  }
  if (t < CB) g_start[t] = sc[t] - cnts[t];
  if (t == CB - 1) g_total = sc[t];
}

// =====================================================================
// fusedA: heterogeneous kernel, one wave (R8-proven).
//  blocks [0,256):  per-batch compaction maps + zero g_x/g_v
//  blocks [256,292): K0 tiles: g_MT = (scale*WQ@WK^T)^T fp16
// =====================================================================
__global__ void __launch_bounds__(256, 1) fusedA(
    const float* __restrict__ WQ, const float* __restrict__ WKm, float cscale,
    const int* __restrict__ ctx_mask, const int* __restrict__ cand_mask) {
  extern __shared__ unsigned smem_u[];

  if (blockIdx.x < 256) {
    __shared__ int wsum[8], wsum2[8];
    const int b = blockIdx.x, t = threadIdx.x, lane = t & 31, w = t >> 5;
    g_x[b * CL + t] = 0.f;
    g_v[b * 256 + t] = 0.f;
    int m = ctx_mask[b * CL + t];
    unsigned bal = __ballot_sync(~0u, m != 0);
    int wr = __popc(bal & ((1u << lane) - 1));
    int m2 = (t < CS) ? cand_mask[b * CS + t] : 0;
    unsigned bal2 = __ballot_sync(~0u, m2 != 0);
    int wr2 = __popc(bal2 & ((1u << lane) - 1));
    if (lane == 0) {
      wsum[w] = __popc(bal);
      wsum2[w] = __popc(bal2);
    }
    __syncthreads();
    int off = 0, off2 = 0;
    for (int i = 0; i < w; i++) {
      off += wsum[i];
      off2 += wsum2[i];
    }
    if (m) g_rowmap[g_start[b] + off + wr] = b * CL + t;
    if (m2) g_colmap[b * 256 + off2 + wr2] = t;
    return;
  }

  // ---- K0 tile ----
  constexpr int K = CD, N = CD;
  constexpr int ASTR = 36;
  constexpr int BSTR = 132;
  unsigned* As = smem_u;
  unsigned* Bs = smem_u + 2 * 128 * ASTR;

  const int tileid = blockIdx.x - 256;
  const int bm = tileid / 6, bn = tileid % 6;
  const int tid = threadIdx.x;
  const int lane = tid & 31, warp = tid >> 5;
  const int wm = warp >> 1, wn = warp & 1;
  const int grp = lane >> 2, qd = lane & 3;

  const float* Agp = WQ + (size_t)bm * 128 * K;

  float acc[2][8][4];
#pragma unroll
  for (int i = 0; i < 2; i++)
#pragma unroll
    for (int j = 0; j < 8; j++)
#pragma unroll
      for (int t = 0; t < 4; t++) acc[i][j][t] = 0.f;

  float4 ra[4], rb[4];
  auto ldA = [&](int kt) {
#pragma unroll
    for (int i = 0; i < 4; i++) {
      int f = tid + i * 256, r = f >> 3, c = f & 7;
      ra[i] = *(reinterpret_cast<const float4*>(Agp + (size_t)r * K + kt * 32) + c);
    }
  };
  auto ldB = [&](int kt) {
#pragma unroll
    for (int i = 0; i < 4; i++) {
      int f = tid + i * 256, r = f >> 3, c = f & 7;
      rb[i] = *(reinterpret_cast<const float4*>(WKm + (size_t)(bn * 128 + r) * K + kt * 32) + c);
    }
  };
  auto stA = [&](int buf) {
    unsigned* ap = As + buf * 128 * ASTR;
#pragma unroll
    for (int i = 0; i < 4; i++) {
      int f = tid + i * 256, r = f >> 3, c = f & 7;
      unsigned* p = ap + r * ASTR + c * 4;
      p[0] = f2tf(ra[i].x); p[1] = f2tf(ra[i].y); p[2] = f2tf(ra[i].z); p[3] = f2tf(ra[i].w);
    }
  };
  auto stB = [&](int buf) {
    unsigned* bp = Bs + buf * 32 * BSTR;
#pragma unroll
    for (int i = 0; i < 4; i++) {
      int f = tid + i * 256, r = f >> 3, c = f & 7;
      bp[(c * 4 + 0) * BSTR + r] = f2tf(rb[i].x);
      bp[(c * 4 + 1) * BSTR + r] = f2tf(rb[i].y);
      bp[(c * 4 + 2) * BSTR + r] = f2tf(rb[i].z);
      bp[(c * 4 + 3) * BSTR + r] = f2tf(rb[i].w);
    }
  };
  auto compute = [&](int buf) {
    const unsigned* ap = As + buf * 128 * ASTR;
    const unsigned* bp = Bs + buf * 32 * BSTR;
#pragma unroll
    for (int ks = 0; ks < 4; ks++) {
      unsigned afr[2][4];
#pragma unroll
      for (int mi = 0; mi < 2; mi++) {
        int row = wm * 32 + mi * 16 + grp;
        afr[mi][0] = ap[row * ASTR + ks * 8 + qd];
        afr[mi][1] = ap[(row + 8) * ASTR + ks * 8 + qd];
        afr[mi][2] = ap[row * ASTR + ks * 8 + qd + 4];
        afr[mi][3] = ap[(row + 8) * ASTR + ks * 8 + qd + 4];
      }
#pragma unroll
      for (int ni = 0; ni < 8; ni++) {
        int col = wn * 64 + ni * 8 + grp;
        unsigned b0 = bp[(ks * 8 + qd) * BSTR + col];
        unsigned b1 = bp[(ks * 8 + qd + 4) * BSTR + col];
        mma8(acc[0][ni], afr[0], b0, b1);
        mma8(acc[1][ni], afr[1], b0, b1);
      }
    }
  };

  const int KT = K / 32;
  ldA(0); ldB(0); stA(0); stB(0);
  __syncthreads();
  for (int kt = 0; kt < KT; ++kt) {
    if (kt + 1 < KT) { ldA(kt + 1); ldB(kt + 1); }
    compute(kt & 1);
    if (kt + 1 < KT) { stA((kt + 1) & 1); stB((kt + 1) & 1); }
    __syncthreads();
  }

  // transposed fp16 store: g_MT[e][d] = C[d][e]
#pragma unroll
  for (int mi = 0; mi < 2; mi++)
#pragma unroll
    for (int ni = 0; ni < 8; ni++) {
      int r0 = bm * 128 + wm * 32 + mi * 16 + grp;
      int c0 = bn * 128 + wn * 64 + ni * 8 + qd * 2;
      g_MT[(size_t)c0 * N + r0] = __float2half(acc[mi][ni][0] * cscale);
      g_MT[(size_t)(c0 + 1) * N + r0] = __float2half(acc[mi][ni][1] * cscale);
      g_MT[(size_t)c0 * N + r0 + 8] = __float2half(acc[mi][ni][2] * cscale);
      g_MT[(size_t)(c0 + 1) * N + r0 + 8] = __float2half(acc[mi][ni][3] * cscale);
    }
}

// =====================================================================
// copy_all: merged gather/convert, grid (16, 256). slice<8 -> ctx rows,
// slice>=8 -> cand rows with fused v' dot (single cand read, R13-proven
// at 61% HBM). Warp-per-row, lane-strided float4.
// =====================================================================
__global__ void __launch_bounds__(256) copy_all(const float* __restrict__ ctx,
                                                const float* __restrict__ cand,
                                                const float* __restrict__ WV) {
  __shared__ int rmap[32];
  const int b = blockIdx.y;
  const int t = threadIdx.x, lane = t & 31, w = t >> 5;

  if (blockIdx.x < 8) {
    const int slice = blockIdx.x;
    const int cnt = g_cnt[b], start = g_start[b];
    const int r0 = slice * 32;
    if (t < 32 && r0 + t < cnt) rmap[t] = g_rowmap[start + r0 + t] - b * CL;
    __syncthreads();
    const int nrows = min(32, cnt - r0);
    for (int row = w; row < nrows; row += 8) {
      const float4* src = (const float4*)(ctx + ((size_t)b * CL + rmap[row]) * CD);
      uint2* dst = (uint2*)(g_ctx_c + (size_t)(start + r0 + row) * CD);
#pragma unroll
      for (int j = 0; j < 6; j++) {
        float4 v = src[lane + j * 32];
        dst[lane + j * 32] = make_uint2(pack2h(v.x, v.y), pack2h(v.z, v.w));
      }
    }
  } else {
    const int slice = blockIdx.x - 8;
    const int cs = g_cnt_s[b];
    const int r0 = slice * 32;
    if (t < 32 && r0 + t < cs) rmap[t] = g_colmap[b * 256 + r0 + t];
    __syncthreads();
    const int nrows = min(32, cs - r0);
    const float4* wv4 = (const float4*)WV;
    for (int row = w; row < nrows; row += 8) {
      const float4* src = (const float4*)(cand + ((size_t)b * CS + rmap[row]) * CD);
      uint2* dst = (uint2*)(g_cand_c + ((size_t)b * 256 + r0 + row) * CD);
      float p = 0.f;
#pragma unroll
      for (int j = 0; j < 6; j++) {
        float4 v = src[lane + j * 32];
        float4 y = wv4[lane + j * 32];
        p += v.x * y.x + v.y * y.y + v.z * y.z + v.w * y.w;
        dst[lane + j * 32] = make_uint2(pack2h(v.x, v.y), pack2h(v.z, v.w));
      }
#pragma unroll
      for (int o = 16; o > 0; o >>= 1) p += __shfl_xor_sync(~0u, p, o);
      if (lane == 0) g_v[b * 256 + r0 + row] = p;
    }
  }
}

// =====================================================================
// Unified 128x128xK=768 fp16 mainloop (proven R8 config): m16n8k16,
// ldmatrix b16 fragments, 3-stage cp.async, 8 warps 32x64 tiles,
// 2 CTAs/SM.
// MODE 0 (qgemm): A = ctx_c rows, B = g_MT,   epilogue: store q'' fp16
// MODE 1 (agemm): mt=0 ONLY (rows 0..127 per batch; overflow rows go
//                 to rem_attn). A = q_c rows, B = cand_c.
// =====================================================================
template <int MODE>
__global__ void __launch_bounds__(256, 2) mm_main() {
  extern __shared__ char sm[];
  const int tid = threadIdx.x, lane = tid & 31, warp = tid >> 5;
  const int wm = warp >> 1, wn = warp & 1;
  const int grp = lane >> 2, qd = lane & 3;

  const char* Abase;
  const char* Bbase;
  int b = 0, nt = 0, cnt = 0, start = 0;
  if (MODE == 0) {
    int ptot = (g_total + 127) & ~127;
    if ((int)blockIdx.y * 128 >= ptot) return;
    Abase = (const char*)(g_ctx_c + (size_t)blockIdx.y * 128 * CD);
    Bbase = (const char*)(g_MT + (size_t)blockIdx.x * 128 * CD);
  } else {
    b = blockIdx.y; nt = blockIdx.x;
    cnt = g_cnt[b];
    int cs = g_cnt_s[b];
    if (cnt == 0 || nt * 128 >= cs) return;
    start = g_start[b];
    Abase = (const char*)(g_qc + (size_t)start * CD);
    Bbase = (const char*)(g_cand_c + ((size_t)b * 256 + nt * 128) * CD);
  }

  float* v_s = (float*)sm;          // [128]
  float* x_s = (float*)(sm + 512);  // [128]
  char* stg = sm + 1024;
  const uint32_t sb = smem_u32(stg);
  constexpr int RSTR = 144;          // 64 halves (128B) + 16B pad, conflict-free
  constexpr int ASZ = 128 * RSTR;    // 18432
  constexpr int STG = 2 * ASZ;       // 36864
  constexpr int KT = CD / 64;        // 12 k-tiles

  if (MODE == 1 && tid < 128) {
    x_s[tid] = 0.f;
    v_s[tid] = g_v[b * 256 + nt * 128 + tid];
  }

  // ldmatrix per-lane byte offsets (fp16 m16n8k16 canonical x4 pattern)
  const int l7 = lane & 7, lb3 = (lane >> 3) & 1, lb4 = lane >> 4;
  const uint32_t a_base0 = (uint32_t)((wm * 32 + l7 + lb3 * 8) * RSTR + lb4 * 16);
  const uint32_t a_base1 = a_base0 + 16 * RSTR;
  uint32_t b_base[4];
#pragma unroll
  for (int j = 0; j < 4; j++)
    b_base[j] = (uint32_t)((wn * 64 + j * 16 + l7 + lb4 * 8) * RSTR + lb3 * 16);

  float acc[2][8][4];
#pragma unroll
  for (int i = 0; i < 2; i++)
#pragma unroll
    for (int j = 0; j < 8; j++)
#pragma unroll
      for (int t = 0; t < 4; t++) acc[i][j][t] = 0.f;

  auto issue = [&](int kt) {
    if (kt < KT) {
      int s = kt - (kt / 3) * 3;
      uint32_t ab = sb + s * STG, bb = ab + ASZ;
#pragma unroll
      for (int i = 0; i < 4; i++) {
        int f = tid + i * 256, r = f >> 3, c = f & 7;
        cp16(ab + r * RSTR + c * 16, Abase + (size_t)r * 1536 + kt * 128 + c * 16);
        cp16(bb + r * RSTR + c * 16, Bbase + (size_t)r * 1536 + kt * 128 + c * 16);
      }
    }
    CP_COMMIT();
  };

  issue(0);
  issue(1);
  for (int kt = 0; kt < KT; ++kt) {
    CP_WAIT1();
    __syncthreads();
    issue(kt + 2);
    const int s = kt - (kt / 3) * 3;
    const uint32_t abp = sb + s * STG;
    const uint32_t bbp = abp + ASZ;
#pragma unroll
    for (int ks = 0; ks < 4; ks++) {
      const uint32_t ka = ks * 32;  // k16 = 32 bytes
      unsigned a0[4], a1[4];
      LDSM_X4(a0[0], a0[1], a0[2], a0[3], abp + a_base0 + ka);
      LDSM_X4(a1[0], a1[1], a1[2], a1[3], abp + a_base1 + ka);
#pragma unroll
      for (int j = 0; j < 4; j++) {
        unsigned bf0, bf1, bf2, bf3;
        LDSM_X4(bf0, bf1, bf2, bf3, bbp + b_base[j] + ka);
        mma16(acc[0][2 * j], a0, bf0, bf1);
        mma16(acc[1][2 * j], a1, bf0, bf1);
        mma16(acc[0][2 * j + 1], a0, bf2, bf3);
        mma16(acc[1][2 * j + 1], a1, bf2, bf3);
      }
    }
  }

  if (MODE == 0) {
    const int i0 = blockIdx.y * 128, bn = blockIdx.x;
#pragma unroll
    for (int mi = 0; mi < 2; mi++)
#pragma unroll
      for (int ni = 0; ni < 8; ni++) {
        int r = wm * 32 + mi * 16 + grp;
        int c = bn * 128 + wn * 64 + ni * 8 + qd * 2;
        size_t o = (size_t)(i0 + r) * CD + c;
        *(uint32_t*)(g_qc + o) = pack2h(acc[mi][ni][0], acc[mi][ni][1]);
        o += (size_t)8 * CD;
        *(uint32_t*)(g_qc + o) = pack2h(acc[mi][ni][2], acc[mi][ni][3]);
      }
  } else {
    float xp[2][2] = {{0.f, 0.f}, {0.f, 0.f}};
#pragma unroll
    for (int mi = 0; mi < 2; mi++)
#pragma unroll
      for (int ni = 0; ni < 8; ni++) {
        int c0 = wn * 64 + ni * 8 + qd * 2;
        float va = v_s[c0], vb = v_s[c0 + 1];
        xp[mi][0] += va / (1.f + __expf(-acc[mi][ni][0])) + vb / (1.f + __expf(-acc[mi][ni][1]));
        xp[mi][1] += va / (1.f + __expf(-acc[mi][ni][2])) + vb / (1.f + __expf(-acc[mi][ni][3]));
      }
#pragma unroll
    for (int mi = 0; mi < 2; mi++)
#pragma unroll
      for (int rs = 0; rs < 2; rs++) {
        float v = xp[mi][rs];
        v += __shfl_xor_sync(0xffffffffu, v, 1);
        v += __shfl_xor_sync(0xffffffffu, v, 2);
        if (qd == 0) atomicAdd(&x_s[wm * 32 + mi * 16 + rs * 8 + grp], v);
      }
    __syncthreads();
    if (tid < 128 && tid < cnt)
      atomicAdd(&g_x[g_rowmap[start + tid]], x_s[tid]);
  }
}

// =====================================================================
// rem_attn: overflow rows (per-batch index 128..cnt-1; ~800 chip-wide).
// One CTA per row: q row staged as float2 smem, warp-per-candidate fp32
// dot + sigmoid*v'. grid (128, CB); nearly all CTAs exit instantly.
// =====================================================================
__global__ void __launch_bounds__(256) rem_attn() {
  const int b = blockIdx.y;
  const int cnt = g_cnt[b];
  const int ridx = 128 + blockIdx.x;
  if (ridx >= cnt) return;
  const int cs = g_cnt_s[b], start = g_start[b];
  __shared__ float2 qs[CD / 2];
  __shared__ float xsum[8];
  const int t = threadIdx.x, lane = t & 31, w = t >> 5;

  const __half2* qr = (const __half2*)(g_qc + (size_t)(start + ridx) * CD);
  for (int i = t; i < CD / 2; i += 256) qs[i] = __half22float2(qr[i]);
  __syncthreads();

  float xw = 0.f;
  for (int s = w; s < cs; s += 8) {
    const __half2* kr = (const __half2*)(g_cand_c + ((size_t)b * 256 + s) * CD);
    float p = 0.f;
#pragma unroll
    for (int j = 0; j < 12; j++) {  // 384 half2 = 32 lanes x 12
      float2 f = __half22float2(kr[lane + j * 32]);
      float2 q2 = qs[lane + j * 32];
      p += f.x * q2.x + f.y * q2.y;
    }
#pragma unroll
    for (int o = 16; o > 0; o >>= 1) p += __shfl_xor_sync(~0u, p, o);
    if (lane == 0) xw += g_v[b * 256 + s] / (1.f + __expf(-p));
  }
  if (lane == 0) xsum[w] = xw;
  __syncthreads();
  if (t == 0) {
    float x = 0.f;
#pragma unroll
    for (int i = 0; i < 8; i++) x += xsum[i];
    g_x[g_rowmap[start + ridx]] = x;  // unique writer for this row
  }
}

// =====================================================================
// Head: y[b,:] = (x_b @ W1 + b1) @ W2 + b2.
// =====================================================================
__global__ void head_kernel(const float* __restrict__ W1, const float* __restrict__ b1,
                            const float* __restrict__ W2, const float* __restrict__ b2,
                            float* __restrict__ out) {
  __shared__ float xs[CL];
  __shared__ float hs[CH];
  int b = blockIdx.x, tid = threadIdx.x;
  xs[tid] = g_x[b * CL + tid];
  xs[tid + 128] = g_x[b * CL + tid + 128];
  __syncthreads();
  float h = b1[tid];
  for (int l = 0; l < CL; l++) h += xs[l] * W1[l * CH + tid];
  hs[tid] = h;
  __syncthreads();
  if (tid < 5) {
    float y = b2[tid];
    for (int k = 0; k < CH; k++) y += hs[k] * W2[k * 5 + tid];
    out[b * 5 + tid] = y;
  }
}

extern "C" void kernel_launch(void* const* d_in, const int* in_sizes, int n_in,
                              void* d_out, int out_size) {
  const float* ctx = (const float*)d_in[0];
  const float* cand = (const float*)d_in[1];
  const int* ctx_mask = (const int*)d_in[2];
  const int* cand_mask = (const int*)d_in[3];
  const float* WK = (const float*)d_in[4];
  const float* WQ = (const float*)d_in[5];
  const float* WV = (const float*)d_in[6];
  const float* W1 = (const float*)d_in[7];
  const float* b1 = (const float*)d_in[8];
  const float* W2 = (const float*)d_in[9];
  const float* b2 = (const float*)d_in[10];
  float* out = (float*)d_out;
  (void)in_sizes; (void)n_in; (void)out_size;

  constexpr int GEMM_SMEM = (2 * 128 * 36 + 2 * 32 * 132) * 4;  // 70656
  constexpr int MM_SMEM = 1024 + 3 * (2 * 128 * 144);           // 111616

  cudaFuncSetAttribute(fusedA, cudaFuncAttributeMaxDynamicSharedMemorySize, GEMM_SMEM);
  cudaFuncSetAttribute(mm_main<0>, cudaFuncAttributeMaxDynamicSharedMemorySize, MM_SMEM);
  cudaFuncSetAttribute(mm_main<1>, cudaFuncAttributeMaxDynamicSharedMemorySize, MM_SMEM);

  float scale = 1.0f / sqrtf((float)CD);

  // 0: mask counts + prefix (parallelized)
  scan1<<<1, 1024>>>(ctx_mask, cand_mask);
  // 1: fused heterogeneous wave: compaction maps (256 blocks) || K0 (36 blocks)
  fusedA<<<292, 256, GEMM_SMEM>>>(WQ, WK, scale, ctx_mask, cand_mask);
  // 2: merged gather/convert (ctx + cand with fused v')
  copy_all<<<dim3(16, CB), 256>>>(ctx, cand, WV);
  // 3 (profiled): q_c = ctx_c @ M  (proven R8 fp16 mainloop)
  mm_main<0><<<dim3(CD / 128, (CB * CL) / 128), 256, MM_SMEM>>>();
  // 4: fused logits -> sigmoid -> x, mt=0 tiles only
  mm_main<1><<<dim3(2, CB), 256, MM_SMEM>>>();
  // 5: overflow rows (>=128 per batch) via fp32 dot kernel
  rem_attn<<<dim3(128, CB), 256>>>();
  // 6: head MLP -> y
  head_kernel<<<CB, CH>>>(W1, b1, W2, b2, out);
}

// round 15
// speedup vs baseline: 1.0914x; 1.0914x over previous
#include <cuda_runtime.h>
#include <cuda_fp16.h>
#include <math.h>
#include <stdint.h>

#define CB 256
#define CL 256
#define CS 253
#define CD 768
#define CH 128
#define ROWCAP (CB * CL + 256)

// ---- scratch (static device globals; zero-initialized at module load) ----
__device__ __align__(256) __half g_MT[CD * CD];                   // (s*WQ@WK^T)^T, n-major
__device__ __align__(256) __half g_ctx_c[(size_t)ROWCAP * CD];    // compacted ctx rows
__device__ __align__(256) __half g_qc[(size_t)ROWCAP * CD];       // compacted q'' rows
__device__ __align__(256) __half g_cand_c[(size_t)CB * 256 * CD]; // per-batch compacted cand
__device__ float g_v[CB * 256];   // v' at compacted col positions (0 on pads)
__device__ float g_x[CB * CL];
__device__ int g_rowmap[ROWCAP];
__device__ int g_colmap[CB * 256];
__device__ int g_start[CB];
__device__ int g_cnt[CB];
__device__ int g_cnt_s[CB];
__device__ int g_total;

// =====================================================================
// helpers
// =====================================================================
__device__ __forceinline__ unsigned f2tf(float f) {
  unsigned r;
  asm("cvt.rna.tf32.f32 %0, %1;" : "=r"(r) : "f"(f));
  return r;
}

__device__ __forceinline__ uint32_t smem_u32(const void* p) {
  uint32_t a;
  asm("{ .reg .u64 t; cvta.to.shared.u64 t, %1; cvt.u32.u64 %0, t; }" : "=r"(a) : "l"(p));
  return a;
}

__device__ __forceinline__ void cp16(uint32_t dst, const void* src) {
  asm volatile("cp.async.cg.shared.global [%0], [%1], 16;" ::"r"(dst), "l"(src) : "memory");
}
#define CP_COMMIT() asm volatile("cp.async.commit_group;" ::: "memory")
// 3-stage pipeline, prologue commits 2 groups, loop issues kt+2:
// wait until <=1 pending so stage kt is complete (R5 lesson: NOT 2).
#define CP_WAIT1() asm volatile("cp.async.wait_group 1;" ::: "memory")

// legacy tf32 mma for the tiny K0 (fp32 inputs)
__device__ __forceinline__ void mma8(float c[4], const unsigned a[4],
                                     unsigned b0, unsigned b1) {
  asm volatile(
      "mma.sync.aligned.m16n8k8.row.col.f32.tf32.tf32.f32 "
      "{%0,%1,%2,%3}, {%4,%5,%6,%7}, {%8,%9}, {%0,%1,%2,%3};"
      : "+f"(c[0]), "+f"(c[1]), "+f"(c[2]), "+f"(c[3])
      : "r"(a[0]), "r"(a[1]), "r"(a[2]), "r"(a[3]), "r"(b0), "r"(b1));
}

// fp16 mma, fp32 accumulate
__device__ __forceinline__ void mma16(float c[4], const unsigned a[4],
                                      unsigned b0, unsigned b1) {
  asm volatile(
      "mma.sync.aligned.m16n8k16.row.col.f32.f16.f16.f32 "
      "{%0,%1,%2,%3}, {%4,%5,%6,%7}, {%8,%9}, {%0,%1,%2,%3};"
      : "+f"(c[0]), "+f"(c[1]), "+f"(c[2]), "+f"(c[3])
      : "r"(a[0]), "r"(a[1]), "r"(a[2]), "r"(a[3]), "r"(b0), "r"(b1));
}

#define LDSM_X4(r0, r1, r2, r3, addr)                                          \
  asm volatile("ldmatrix.sync.aligned.m8n8.x4.shared.b16 {%0,%1,%2,%3}, [%4];" \
               : "=r"(r0), "=r"(r1), "=r"(r2), "=r"(r3)                        \
               : "r"(addr))

__device__ __forceinline__ uint32_t pack2h(float a, float b) {
  __half2 h = __floats2half2_rn(a, b);
  return *(uint32_t*)&h;
}

// =====================================================================
// scan1: per-batch mask counts + prefix (parallel, R12-proven).
// =====================================================================
__global__ void __launch_bounds__(1024) scan1(const int* __restrict__ ctx_mask,
                                              const int* __restrict__ cand_mask) {
  __shared__ int sc[CB];
  __shared__ int cnts[CB];
  const int t = threadIdx.x;
  const int b = t >> 2, q = t & 3;

  const int4* cm4 = (const int4*)ctx_mask + b * 64 + q * 16;
  int s = 0;
#pragma unroll
  for (int i = 0; i < 16; i++) {
    int4 v = cm4[i];
    s += v.x + v.y + v.z + v.w;
  }
  s += __shfl_xor_sync(~0u, s, 1);
  s += __shfl_xor_sync(~0u, s, 2);

  const int* smk = cand_mask + b * CS + q * 64;
  const int e = (q == 3) ? (CS - 192) : 64;
  int s2 = 0;
#pragma unroll 8
  for (int i = 0; i < e; i++) s2 += smk[i];
  s2 += __shfl_xor_sync(~0u, s2, 1);
  s2 += __shfl_xor_sync(~0u, s2, 2);

  if (q == 0) {
    g_cnt[b] = s;
    g_cnt_s[b] = s2;
    sc[b] = s;
    cnts[b] = s;
  }
  __syncthreads();
  for (int off = 1; off < CB; off <<= 1) {
    int v = 0;
    if (t < CB && t >= off) v = sc[t - off];
    __syncthreads();
    if (t < CB) sc[t] += v;
    __syncthreads();
  }
  if (t < CB) g_start[t] = sc[t] - cnts[t];
  if (t == CB - 1) g_total = sc[t];
}

// =====================================================================
// fusedA: heterogeneous kernel, one wave (R8-proven).
//  blocks [0,256):  per-batch compaction maps + zero g_x/g_v
//  blocks [256,292): K0 tiles: g_MT = (scale*WQ@WK^T)^T fp16
// =====================================================================
__global__ void __launch_bounds__(256, 1) fusedA(
    const float* __restrict__ WQ, const float* __restrict__ WKm, float cscale,
    const int* __restrict__ ctx_mask, const int* __restrict__ cand_mask) {
  extern __shared__ unsigned smem_u[];

  if (blockIdx.x < 256) {
    __shared__ int wsum[8], wsum2[8];
    const int b = blockIdx.x, t = threadIdx.x, lane = t & 31, w = t >> 5;
    g_x[b * CL + t] = 0.f;
    g_v[b * 256 + t] = 0.f;
    int m = ctx_mask[b * CL + t];
    unsigned bal = __ballot_sync(~0u, m != 0);
    int wr = __popc(bal & ((1u << lane) - 1));
    int m2 = (t < CS) ? cand_mask[b * CS + t] : 0;
    unsigned bal2 = __ballot_sync(~0u, m2 != 0);
    int wr2 = __popc(bal2 & ((1u << lane) - 1));
    if (lane == 0) {
      wsum[w] = __popc(bal);
      wsum2[w] = __popc(bal2);
    }
    __syncthreads();
    int off = 0, off2 = 0;
    for (int i = 0; i < w; i++) {
      off += wsum[i];
      off2 += wsum2[i];
    }
    if (m) g_rowmap[g_start[b] + off + wr] = b * CL + t;
    if (m2) g_colmap[b * 256 + off2 + wr2] = t;
    return;
  }

  // ---- K0 tile ----
  constexpr int K = CD, N = CD;
  constexpr int ASTR = 36;
  constexpr int BSTR = 132;
  unsigned* As = smem_u;
  unsigned* Bs = smem_u + 2 * 128 * ASTR;

  const int tileid = blockIdx.x - 256;
  const int bm = tileid / 6, bn = tileid % 6;
  const int tid = threadIdx.x;
  const int lane = tid & 31, warp = tid >> 5;
  const int wm = warp >> 1, wn = warp & 1;
  const int grp = lane >> 2, qd = lane & 3;

  const float* Agp = WQ + (size_t)bm * 128 * K;

  float acc[2][8][4];
#pragma unroll
  for (int i = 0; i < 2; i++)
#pragma unroll
    for (int j = 0; j < 8; j++)
#pragma unroll
      for (int t = 0; t < 4; t++) acc[i][j][t] = 0.f;

  float4 ra[4], rb[4];
  auto ldA = [&](int kt) {
#pragma unroll
    for (int i = 0; i < 4; i++) {
      int f = tid + i * 256, r = f >> 3, c = f & 7;
      ra[i] = *(reinterpret_cast<const float4*>(Agp + (size_t)r * K + kt * 32) + c);
    }
  };
  auto ldB = [&](int kt) {
#pragma unroll
    for (int i = 0; i < 4; i++) {
      int f = tid + i * 256, r = f >> 3, c = f & 7;
      rb[i] = *(reinterpret_cast<const float4*>(WKm + (size_t)(bn * 128 + r) * K + kt * 32) + c);
    }
  };
  auto stA = [&](int buf) {
    unsigned* ap = As + buf * 128 * ASTR;
#pragma unroll
    for (int i = 0; i < 4; i++) {
      int f = tid + i * 256, r = f >> 3, c = f & 7;
      unsigned* p = ap + r * ASTR + c * 4;
      p[0] = f2tf(ra[i].x); p[1] = f2tf(ra[i].y); p[2] = f2tf(ra[i].z); p[3] = f2tf(ra[i].w);
    }
  };
  auto stB = [&](int buf) {
    unsigned* bp = Bs + buf * 32 * BSTR;
#pragma unroll
    for (int i = 0; i < 4; i++) {
      int f = tid + i * 256, r = f >> 3, c = f & 7;
      bp[(c * 4 + 0) * BSTR + r] = f2tf(rb[i].x);
      bp[(c * 4 + 1) * BSTR + r] = f2tf(rb[i].y);
      bp[(c * 4 + 2) * BSTR + r] = f2tf(rb[i].z);
      bp[(c * 4 + 3) * BSTR + r] = f2tf(rb[i].w);
    }
  };
  auto compute = [&](int buf) {
    const unsigned* ap = As + buf * 128 * ASTR;
    const unsigned* bp = Bs + buf * 32 * BSTR;
#pragma unroll
    for (int ks = 0; ks < 4; ks++) {
      unsigned afr[2][4];
#pragma unroll
      for (int mi = 0; mi < 2; mi++) {
        int row = wm * 32 + mi * 16 + grp;
        afr[mi][0] = ap[row * ASTR + ks * 8 + qd];
        afr[mi][1] = ap[(row + 8) * ASTR + ks * 8 + qd];
        afr[mi][2] = ap[row * ASTR + ks * 8 + qd + 4];
        afr[mi][3] = ap[(row + 8) * ASTR + ks * 8 + qd + 4];
      }
#pragma unroll
      for (int ni = 0; ni < 8; ni++) {
        int col = wn * 64 + ni * 8 + grp;
        unsigned b0 = bp[(ks * 8 + qd) * BSTR + col];
        unsigned b1 = bp[(ks * 8 + qd + 4) * BSTR + col];
        mma8(acc[0][ni], afr[0], b0, b1);
        mma8(acc[1][ni], afr[1], b0, b1);
      }
    }
  };

  const int KT = K / 32;
  ldA(0); ldB(0); stA(0); stB(0);
  __syncthreads();
  for (int kt = 0; kt < KT; ++kt) {
    if (kt + 1 < KT) { ldA(kt + 1); ldB(kt + 1); }
    compute(kt & 1);
    if (kt + 1 < KT) { stA((kt + 1) & 1); stB((kt + 1) & 1); }
    __syncthreads();
  }

  // transposed fp16 store: g_MT[e][d] = C[d][e]
#pragma unroll
  for (int mi = 0; mi < 2; mi++)
#pragma unroll
    for (int ni = 0; ni < 8; ni++) {
      int r0 = bm * 128 + wm * 32 + mi * 16 + grp;
      int c0 = bn * 128 + wn * 64 + ni * 8 + qd * 2;
      g_MT[(size_t)c0 * N + r0] = __float2half(acc[mi][ni][0] * cscale);
      g_MT[(size_t)(c0 + 1) * N + r0] = __float2half(acc[mi][ni][1] * cscale);
      g_MT[(size_t)c0 * N + r0 + 8] = __float2half(acc[mi][ni][2] * cscale);
      g_MT[(size_t)(c0 + 1) * N + r0 + 8] = __float2half(acc[mi][ni][3] * cscale);
    }
}

// =====================================================================
// copy_ctx: warp-per-row gather+convert (R13-proven). grid (8, 256).
// =====================================================================
__global__ void __launch_bounds__(256) copy_ctx(const float* __restrict__ ctx) {
  __shared__ int lr[32];
  const int b = blockIdx.y, slice = blockIdx.x;
  const int t = threadIdx.x, lane = t & 31, w = t >> 5;
  const int cnt = g_cnt[b], start = g_start[b];
  const int r0 = slice * 32;
  if (t < 32 && r0 + t < cnt) lr[t] = g_rowmap[start + r0 + t] - b * CL;
  __syncthreads();
  const int nrows = min(32, cnt - r0);
  for (int row = w; row < nrows; row += 8) {
    const float4* src = (const float4*)(ctx + ((size_t)b * CL + lr[row]) * CD);
    uint2* dst = (uint2*)(g_ctx_c + (size_t)(start + r0 + row) * CD);
#pragma unroll
    for (int j = 0; j < 6; j++) {
      float4 v = src[lane + j * 32];
      dst[lane + j * 32] = make_uint2(pack2h(v.x, v.y), pack2h(v.z, v.w));
    }
  }
}

// =====================================================================
// copy_cand: warp-per-row gather+convert with fused v' dot (R13-proven
// at 61% HBM; single cand read). grid (8, 256). Runs on a FORKED stream
// concurrent with copy_ctx + mm0 (depends only on fusedA's maps).
// =====================================================================
__global__ void __launch_bounds__(256) copy_cand(const float* __restrict__ cand,
                                                 const float* __restrict__ WV) {
  __shared__ int sr[32];
  const int b = blockIdx.y, slice = blockIdx.x;
  const int t = threadIdx.x, lane = t & 31, w = t >> 5;
  const int cs = g_cnt_s[b];
  const int r0 = slice * 32;
  if (t < 32 && r0 + t < cs) sr[t] = g_colmap[b * 256 + r0 + t];
  __syncthreads();
  const int nrows = min(32, cs - r0);
  const float4* wv4 = (const float4*)WV;
  for (int row = w; row < nrows; row += 8) {
    const float4* src = (const float4*)(cand + ((size_t)b * CS + sr[row]) * CD);
    uint2* dst = (uint2*)(g_cand_c + ((size_t)b * 256 + r0 + row) * CD);
    float p = 0.f;
#pragma unroll
    for (int j = 0; j < 6; j++) {
      float4 v = src[lane + j * 32];
      float4 y = wv4[lane + j * 32];
      p += v.x * y.x + v.y * y.y + v.z * y.z + v.w * y.w;
      dst[lane + j * 32] = make_uint2(pack2h(v.x, v.y), pack2h(v.z, v.w));
    }
#pragma unroll
    for (int o = 16; o > 0; o >>= 1) p += __shfl_xor_sync(~0u, p, o);
    if (lane == 0) g_v[b * 256 + r0 + row] = p;
  }
}

// =====================================================================
// Unified 128x128xK=768 fp16 mainloop (proven R8 config): m16n8k16,
// ldmatrix b16 fragments, 3-stage cp.async, 8 warps 32x64 tiles,
// 2 CTAs/SM.
// MODE 0 (qgemm):  A = ctx_c rows, B = g_MT,    epilogue: store q'' fp16
// MODE 1 (agemm):  A = q_c rows,   B = cand_c,  epilogue: sigmoid*v -> x
// =====================================================================
template <int MODE>
__global__ void __launch_bounds__(256, 2) mm_main() {
  extern __shared__ char sm[];
  const int tid = threadIdx.x, lane = tid & 31, warp = tid >> 5;
  const int wm = warp >> 1, wn = warp & 1;
  const int grp = lane >> 2, qd = lane & 3;

  const char* Abase;
  const char* Bbase;
  int b = 0, mt = 0, nt = 0, cnt = 0, start = 0;
  if (MODE == 0) {
    int ptot = (g_total + 127) & ~127;
    if ((int)blockIdx.y * 128 >= ptot) return;
    Abase = (const char*)(g_ctx_c + (size_t)blockIdx.y * 128 * CD);
    Bbase = (const char*)(g_MT + (size_t)blockIdx.x * 128 * CD);
  } else {
    b = blockIdx.y; mt = blockIdx.x >> 1; nt = blockIdx.x & 1;
    cnt = g_cnt[b];
    int cs = g_cnt_s[b];
    if (mt * 128 >= cnt || nt * 128 >= cs) return;
    start = g_start[b];
    Abase = (const char*)(g_qc + (size_t)(start + mt * 128) * CD);
    Bbase = (const char*)(g_cand_c + ((size_t)b * 256 + nt * 128) * CD);
  }

  float* v_s = (float*)sm;          // [128]
  float* x_s = (float*)(sm + 512);  // [128]
  char* stg = sm + 1024;
  const uint32_t sb = smem_u32(stg);
  constexpr int RSTR = 144;          // 64 halves (128B) + 16B pad, conflict-free
  constexpr int ASZ = 128 * RSTR;    // 18432
  constexpr int STG = 2 * ASZ;       // 36864
  constexpr int KT = CD / 64;        // 12 k-tiles

  if (MODE == 1 && tid < 128) {
    x_s[tid] = 0.f;
    v_s[tid] = g_v[b * 256 + nt * 128 + tid];
  }

  // ldmatrix per-lane byte offsets (fp16 m16n8k16 canonical x4 pattern)
  const int l7 = lane & 7, lb3 = (lane >> 3) & 1, lb4 = lane >> 4;
  const uint32_t a_base0 = (uint32_t)((wm * 32 + l7 + lb3 * 8) * RSTR + lb4 * 16);
  const uint32_t a_base1 = a_base0 + 16 * RSTR;
  uint32_t b_base[4];
#pragma unroll
  for (int j = 0; j < 4; j++)
    b_base[j] = (uint32_t)((wn * 64 + j * 16 + l7 + lb4 * 8) * RSTR + lb3 * 16);

  float acc[2][8][4];
#pragma unroll
  for (int i = 0; i < 2; i++)
#pragma unroll
    for (int j = 0; j < 8; j++)
#pragma unroll
      for (int t = 0; t < 4; t++) acc[i][j][t] = 0.f;

  auto issue = [&](int kt) {
    if (kt < KT) {
      int s = kt - (kt / 3) * 3;
      uint32_t ab = sb + s * STG, bb = ab + ASZ;
#pragma unroll
      for (int i = 0; i < 4; i++) {
        int f = tid + i * 256, r = f >> 3, c = f & 7;
        cp16(ab + r * RSTR + c * 16, Abase + (size_t)r * 1536 + kt * 128 + c * 16);
        cp16(bb + r * RSTR + c * 16, Bbase + (size_t)r * 1536 + kt * 128 + c * 16);
      }
    }
    CP_COMMIT();
  };

  issue(0);
  issue(1);
  for (int kt = 0; kt < KT; ++kt) {
    CP_WAIT1();
    __syncthreads();
    issue(kt + 2);
    const int s = kt - (kt / 3) * 3;
    const uint32_t abp = sb + s * STG;
    const uint32_t bbp = abp + ASZ;
#pragma unroll
    for (int ks = 0; ks < 4; ks++) {
      const uint32_t ka = ks * 32;  // k16 = 32 bytes
      unsigned a0[4], a1[4];
      LDSM_X4(a0[0], a0[1], a0[2], a0[3], abp + a_base0 + ka);
      LDSM_X4(a1[0], a1[1], a1[2], a1[3], abp + a_base1 + ka);
#pragma unroll
      for (int j = 0; j < 4; j++) {
        unsigned bf0, bf1, bf2, bf3;
        LDSM_X4(bf0, bf1, bf2, bf3, bbp + b_base[j] + ka);
        mma16(acc[0][2 * j], a0, bf0, bf1);
        mma16(acc[1][2 * j], a1, bf0, bf1);
        mma16(acc[0][2 * j + 1], a0, bf2, bf3);
        mma16(acc[1][2 * j + 1], a1, bf2, bf3);
      }
    }
  }

  if (MODE == 0) {
    const int i0 = blockIdx.y * 128, bn = blockIdx.x;
#pragma unroll
    for (int mi = 0; mi < 2; mi++)
#pragma unroll
      for (int ni = 0; ni < 8; ni++) {
        int r = wm * 32 + mi * 16 + grp;
        int c = bn * 128 + wn * 64 + ni * 8 + qd * 2;
        size_t o = (size_t)(i0 + r) * CD + c;
        *(uint32_t*)(g_qc + o) = pack2h(acc[mi][ni][0], acc[mi][ni][1]);
        o += (size_t)8 * CD;
        *(uint32_t*)(g_qc + o) = pack2h(acc[mi][ni][2], acc[mi][ni][3]);
      }
  } else {
    float xp[2][2] = {{0.f, 0.f}, {0.f, 0.f}};
#pragma unroll
    for (int mi = 0; mi < 2; mi++)
#pragma unroll
      for (int ni = 0; ni < 8; ni++) {
        int c0 = wn * 64 + ni * 8 + qd * 2;
        float va = v_s[c0], vb = v_s[c0 + 1];
        xp[mi][0] += va / (1.f + __expf(-acc[mi][ni][0])) + vb / (1.f + __expf(-acc[mi][ni][1]));
        xp[mi][1] += va / (1.f + __expf(-acc[mi][ni][2])) + vb / (1.f + __expf(-acc[mi][ni][3]));
      }
#pragma unroll
    for (int mi = 0; mi < 2; mi++)
#pragma unroll
      for (int rs = 0; rs < 2; rs++) {
        float v = xp[mi][rs];
        v += __shfl_xor_sync(0xffffffffu, v, 1);
        v += __shfl_xor_sync(0xffffffffu, v, 2);
        if (qd == 0) atomicAdd(&x_s[wm * 32 + mi * 16 + rs * 8 + grp], v);
      }
    __syncthreads();
    if (tid < 128 && mt * 128 + tid < cnt)
      atomicAdd(&g_x[g_rowmap[start + mt * 128 + tid]], x_s[tid]);
  }
}

// =====================================================================
// Head: y[b,:] = (x_b @ W1 + b1) @ W2 + b2.
// =====================================================================
__global__ void head_kernel(const float* __restrict__ W1, const float* __restrict__ b1,
                            const float* __restrict__ W2, const float* __restrict__ b2,
                            float* __restrict__ out) {
  __shared__ float xs[CL];
  __shared__ float hs[CH];
  int b = blockIdx.x, tid = threadIdx.x;
  xs[tid] = g_x[b * CL + tid];
  xs[tid + 128] = g_x[b * CL + tid + 128];
  __syncthreads();
  float h = b1[tid];
  for (int l = 0; l < CL; l++) h += xs[l] * W1[l * CH + tid];
  hs[tid] = h;
  __syncthreads();
  if (tid < 5) {
    float y = b2[tid];
    for (int k = 0; k < CH; k++) y += hs[k] * W2[k * 5 + tid];
    out[b * 5 + tid] = y;
  }
}

extern "C" void kernel_launch(void* const* d_in, const int* in_sizes, int n_in,
                              void* d_out, int out_size) {
  const float* ctx = (const float*)d_in[0];
  const float* cand = (const float*)d_in[1];
  const int* ctx_mask = (const int*)d_in[2];
  const int* cand_mask = (const int*)d_in[3];
  const float* WK = (const float*)d_in[4];
  const float* WQ = (const float*)d_in[5];
  const float* WV = (const float*)d_in[6];
  const float* W1 = (const float*)d_in[7];
  const float* b1 = (const float*)d_in[8];
  const float* W2 = (const float*)d_in[9];
  const float* b2 = (const float*)d_in[10];
  float* out = (float*)d_out;
  (void)in_sizes; (void)n_in; (void)out_size;

  constexpr int GEMM_SMEM = (2 * 128 * 36 + 2 * 32 * 132) * 4;  // 70656
  constexpr int MM_SMEM = 1024 + 3 * (2 * 128 * 144);           // 111616

  cudaFuncSetAttribute(fusedA, cudaFuncAttributeMaxDynamicSharedMemorySize, GEMM_SMEM);
  cudaFuncSetAttribute(mm_main<0>, cudaFuncAttributeMaxDynamicSharedMemorySize, MM_SMEM);
  cudaFuncSetAttribute(mm_main<1>, cudaFuncAttributeMaxDynamicSharedMemorySize, MM_SMEM);

  // One-time side-stream + events for graph fork-join (created on the
  // uncaptured correctness call; reused identically on every call so the
  // launched work is the same each time). Falls back to sequential legacy-
  // stream launches if creation fails.
  static cudaStream_t s2 = nullptr;
  static cudaEvent_t evA = nullptr, evB = nullptr;
  static int init_ok = -1;
  if (init_ok < 0) {
    init_ok = 1;
    if (cudaStreamCreateWithFlags(&s2, cudaStreamNonBlocking) != cudaSuccess) init_ok = 0;
    if (init_ok && cudaEventCreateWithFlags(&evA, cudaEventDisableTiming) != cudaSuccess) init_ok = 0;
    if (init_ok && cudaEventCreateWithFlags(&evB, cudaEventDisableTiming) != cudaSuccess) init_ok = 0;
  }

  float scale = 1.0f / sqrtf((float)CD);

  // 0: mask counts + prefix (parallelized)
  scan1<<<1, 1024>>>(ctx_mask, cand_mask);
  // 1: fused heterogeneous wave: compaction maps (256 blocks) || K0 (36 blocks)
  fusedA<<<292, 256, GEMM_SMEM>>>(WQ, WK, scale, ctx_mask, cand_mask);

  if (init_ok) {
    // fork: copy_cand runs concurrently with copy_ctx + mm0 on side stream
    cudaEventRecord(evA, 0);
    cudaStreamWaitEvent(s2, evA, 0);
    copy_cand<<<dim3(8, CB), 256, 0, s2>>>(cand, WV);
    cudaEventRecord(evB, s2);
    // main branch
    copy_ctx<<<dim3(8, CB), 256>>>(ctx);
    mm_main<0><<<dim3(CD / 128, (CB * CL) / 128), 256, MM_SMEM>>>();
    // join before mm1 (needs cand_c + g_v)
    cudaStreamWaitEvent(0, evB, 0);
  } else {
    copy_ctx<<<dim3(8, CB), 256>>>(ctx);
    copy_cand<<<dim3(8, CB), 256>>>(cand, WV);
    mm_main<0><<<dim3(CD / 128, (CB * CL) / 128), 256, MM_SMEM>>>();
  }

  // fused logits -> sigmoid -> x  (proven R13 config, full tiling)
  mm_main<1><<<dim3(4, CB), 256, MM_SMEM>>>();
  // head MLP -> y
  head_kernel<<<CB, CH>>>(W1, b1, W2, b2, out);
}

// round 16
// speedup vs baseline: 1.2011x; 1.1006x over previous
#include <cuda_runtime.h>
#include <cuda_fp16.h>
#include <math.h>
#include <stdint.h>

#define CB 256
#define CL 256
#define CS 253
#define CD 768
#define CH 128
#define ROWCAP (CB * CL + 256)

// ---- scratch (static device globals; zero-initialized at module load) ----
__device__ __align__(256) __half g_MT[CD * CD];                   // (s*WQ@WK^T)^T, n-major
__device__ __align__(256) __half g_ctx_c[(size_t)ROWCAP * CD];    // compacted ctx rows
__device__ __align__(256) __half g_qc[(size_t)ROWCAP * CD];       // compacted q'' rows
__device__ __align__(256) __half g_cand_c[(size_t)CB * 256 * CD]; // per-batch compacted cand
__device__ float g_v[CB * 256];   // v' at compacted col positions (0 on pads)
__device__ float g_x[CB * CL];
__device__ int g_rowmap[ROWCAP];
__device__ int g_colmap[CB * 256];
__device__ int g_start[CB];
__device__ int g_cnt[CB];
__device__ int g_cnt_s[CB];
__device__ int g_total;

// =====================================================================
// helpers
// =====================================================================
__device__ __forceinline__ unsigned f2tf(float f) {
  unsigned r;
  asm("cvt.rna.tf32.f32 %0, %1;" : "=r"(r) : "f"(f));
  return r;
}

__device__ __forceinline__ uint32_t smem_u32(const void* p) {
  uint32_t a;
  asm("{ .reg .u64 t; cvta.to.shared.u64 t, %1; cvt.u32.u64 %0, t; }" : "=r"(a) : "l"(p));
  return a;
}

__device__ __forceinline__ void cp16(uint32_t dst, const void* src) {
  asm volatile("cp.async.cg.shared.global [%0], [%1], 16;" ::"r"(dst), "l"(src) : "memory");
}
#define CP_COMMIT() asm volatile("cp.async.commit_group;" ::: "memory")
// 3-stage pipeline, prologue commits 2 groups, loop issues kt+2:
// wait until <=1 pending so stage kt is complete (R5 lesson: NOT 2).
#define CP_WAIT1() asm volatile("cp.async.wait_group 1;" ::: "memory")

// legacy tf32 mma for the tiny K0 (fp32 inputs)
__device__ __forceinline__ void mma8(float c[4], const unsigned a[4],
                                     unsigned b0, unsigned b1) {
  asm volatile(
      "mma.sync.aligned.m16n8k8.row.col.f32.tf32.tf32.f32 "
      "{%0,%1,%2,%3}, {%4,%5,%6,%7}, {%8,%9}, {%0,%1,%2,%3};"
      : "+f"(c[0]), "+f"(c[1]), "+f"(c[2]), "+f"(c[3])
      : "r"(a[0]), "r"(a[1]), "r"(a[2]), "r"(a[3]), "r"(b0), "r"(b1));
}

// fp16 mma, fp32 accumulate
__device__ __forceinline__ void mma16(float c[4], const unsigned a[4],
                                      unsigned b0, unsigned b1) {
  asm volatile(
      "mma.sync.aligned.m16n8k16.row.col.f32.f16.f16.f32 "
      "{%0,%1,%2,%3}, {%4,%5,%6,%7}, {%8,%9}, {%0,%1,%2,%3};"
      : "+f"(c[0]), "+f"(c[1]), "+f"(c[2]), "+f"(c[3])
      : "r"(a[0]), "r"(a[1]), "r"(a[2]), "r"(a[3]), "r"(b0), "r"(b1));
}

#define LDSM_X4(r0, r1, r2, r3, addr)                                          \
  asm volatile("ldmatrix.sync.aligned.m8n8.x4.shared.b16 {%0,%1,%2,%3}, [%4];" \
               : "=r"(r0), "=r"(r1), "=r"(r2), "=r"(r3)                        \
               : "r"(addr))

__device__ __forceinline__ uint32_t pack2h(float a, float b) {
  __half2 h = __floats2half2_rn(a, b);
  return *(uint32_t*)&h;
}

// =====================================================================
// scan1: per-batch mask counts + prefix (parallel, R12-proven).
// =====================================================================
__global__ void __launch_bounds__(1024) scan1(const int* __restrict__ ctx_mask,
                                              const int* __restrict__ cand_mask) {
  __shared__ int sc[CB];
  __shared__ int cnts[CB];
  const int t = threadIdx.x;
  const int b = t >> 2, q = t & 3;

  const int4* cm4 = (const int4*)ctx_mask + b * 64 + q * 16;
  int s = 0;
#pragma unroll
  for (int i = 0; i < 16; i++) {
    int4 v = cm4[i];
    s += v.x + v.y + v.z + v.w;
  }
  s += __shfl_xor_sync(~0u, s, 1);
  s += __shfl_xor_sync(~0u, s, 2);

  const int* smk = cand_mask + b * CS + q * 64;
  const int e = (q == 3) ? (CS - 192) : 64;
  int s2 = 0;
#pragma unroll 8
  for (int i = 0; i < e; i++) s2 += smk[i];
  s2 += __shfl_xor_sync(~0u, s2, 1);
  s2 += __shfl_xor_sync(~0u, s2, 2);

  if (q == 0) {
    g_cnt[b] = s;
    g_cnt_s[b] = s2;
    sc[b] = s;
    cnts[b] = s;
  }
  __syncthreads();
  for (int off = 1; off < CB; off <<= 1) {
    int v = 0;
    if (t < CB && t >= off) v = sc[t - off];
    __syncthreads();
    if (t < CB) sc[t] += v;
    __syncthreads();
  }
  if (t < CB) g_start[t] = sc[t] - cnts[t];
  if (t == CB - 1) g_total = sc[t];
}

// =====================================================================
// maps: per-batch compaction maps + zero g_x/g_v. grid 256 (one/batch).
// =====================================================================
__global__ void __launch_bounds__(256) maps_kernel(
    const int* __restrict__ ctx_mask, const int* __restrict__ cand_mask) {
  __shared__ int wsum[8], wsum2[8];
  const int b = blockIdx.x, t = threadIdx.x, lane = t & 31, w = t >> 5;
  g_x[b * CL + t] = 0.f;
  g_v[b * 256 + t] = 0.f;
  int m = ctx_mask[b * CL + t];
  unsigned bal = __ballot_sync(~0u, m != 0);
  int wr = __popc(bal & ((1u << lane) - 1));
  int m2 = (t < CS) ? cand_mask[b * CS + t] : 0;
  unsigned bal2 = __ballot_sync(~0u, m2 != 0);
  int wr2 = __popc(bal2 & ((1u << lane) - 1));
  if (lane == 0) {
    wsum[w] = __popc(bal);
    wsum2[w] = __popc(bal2);
  }
  __syncthreads();
  int off = 0, off2 = 0;
  for (int i = 0; i < w; i++) {
    off += wsum[i];
    off2 += wsum2[i];
  }
  if (m) g_rowmap[g_start[b] + off + wr] = b * CL + t;
  if (m2) g_colmap[b * 256 + off2 + wr2] = t;
}

// =====================================================================
// k0: g_MT = (scale*WQ@WK^T)^T fp16. grid 36 (6x6 tiles). Depends only
// on inputs -> launched on a side stream at the very start.
// =====================================================================
__global__ void __launch_bounds__(256, 1) k0_kernel(
    const float* __restrict__ WQ, const float* __restrict__ WKm, float cscale) {
  extern __shared__ unsigned smem_u[];
  constexpr int K = CD, N = CD;
  constexpr int ASTR = 36;
  constexpr int BSTR = 132;
  unsigned* As = smem_u;
  unsigned* Bs = smem_u + 2 * 128 * ASTR;

  const int bm = blockIdx.x / 6, bn = blockIdx.x % 6;
  const int tid = threadIdx.x;
  const int lane = tid & 31, warp = tid >> 5;
  const int wm = warp >> 1, wn = warp & 1;
  const int grp = lane >> 2, qd = lane & 3;

  const float* Agp = WQ + (size_t)bm * 128 * K;

  float acc[2][8][4];
#pragma unroll
  for (int i = 0; i < 2; i++)
#pragma unroll
    for (int j = 0; j < 8; j++)
#pragma unroll
      for (int t = 0; t < 4; t++) acc[i][j][t] = 0.f;

  float4 ra[4], rb[4];
  auto ldA = [&](int kt) {
#pragma unroll
    for (int i = 0; i < 4; i++) {
      int f = tid + i * 256, r = f >> 3, c = f & 7;
      ra[i] = *(reinterpret_cast<const float4*>(Agp + (size_t)r * K + kt * 32) + c);
    }
  };
  auto ldB = [&](int kt) {
#pragma unroll
    for (int i = 0; i < 4; i++) {
      int f = tid + i * 256, r = f >> 3, c = f & 7;
      rb[i] = *(reinterpret_cast<const float4*>(WKm + (size_t)(bn * 128 + r) * K + kt * 32) + c);
    }
  };
  auto stA = [&](int buf) {
    unsigned* ap = As + buf * 128 * ASTR;
#pragma unroll
    for (int i = 0; i < 4; i++) {
      int f = tid + i * 256, r = f >> 3, c = f & 7;
      unsigned* p = ap + r * ASTR + c * 4;
      p[0] = f2tf(ra[i].x); p[1] = f2tf(ra[i].y); p[2] = f2tf(ra[i].z); p[3] = f2tf(ra[i].w);
    }
  };
  auto stB = [&](int buf) {
    unsigned* bp = Bs + buf * 32 * BSTR;
#pragma unroll
    for (int i = 0; i < 4; i++) {
      int f = tid + i * 256, r = f >> 3, c = f & 7;
      bp[(c * 4 + 0) * BSTR + r] = f2tf(rb[i].x);
      bp[(c * 4 + 1) * BSTR + r] = f2tf(rb[i].y);
      bp[(c * 4 + 2) * BSTR + r] = f2tf(rb[i].z);
      bp[(c * 4 + 3) * BSTR + r] = f2tf(rb[i].w);
    }
  };
  auto compute = [&](int buf) {
    const unsigned* ap = As + buf * 128 * ASTR;
    const unsigned* bp = Bs + buf * 32 * BSTR;
#pragma unroll
    for (int ks = 0; ks < 4; ks++) {
      unsigned afr[2][4];
#pragma unroll
      for (int mi = 0; mi < 2; mi++) {
        int row = wm * 32 + mi * 16 + grp;
        afr[mi][0] = ap[row * ASTR + ks * 8 + qd];
        afr[mi][1] = ap[(row + 8) * ASTR + ks * 8 + qd];
        afr[mi][2] = ap[row * ASTR + ks * 8 + qd + 4];
        afr[mi][3] = ap[(row + 8) * ASTR + ks * 8 + qd + 4];
      }
#pragma unroll
      for (int ni = 0; ni < 8; ni++) {
        int col = wn * 64 + ni * 8 + grp;
        unsigned b0 = bp[(ks * 8 + qd) * BSTR + col];
        unsigned b1 = bp[(ks * 8 + qd + 4) * BSTR + col];
        mma8(acc[0][ni], afr[0], b0, b1);
        mma8(acc[1][ni], afr[1], b0, b1);
      }
    }
  };

  const int KT = K / 32;
  ldA(0); ldB(0); stA(0); stB(0);
  __syncthreads();
  for (int kt = 0; kt < KT; ++kt) {
    if (kt + 1 < KT) { ldA(kt + 1); ldB(kt + 1); }
    compute(kt & 1);
    if (kt + 1 < KT) { stA((kt + 1) & 1); stB((kt + 1) & 1); }
    __syncthreads();
  }

  // transposed fp16 store: g_MT[e][d] = C[d][e]
#pragma unroll
  for (int mi = 0; mi < 2; mi++)
#pragma unroll
    for (int ni = 0; ni < 8; ni++) {
      int r0 = bm * 128 + wm * 32 + mi * 16 + grp;
      int c0 = bn * 128 + wn * 64 + ni * 8 + qd * 2;
      g_MT[(size_t)c0 * N + r0] = __float2half(acc[mi][ni][0] * cscale);
      g_MT[(size_t)(c0 + 1) * N + r0] = __float2half(acc[mi][ni][1] * cscale);
      g_MT[(size_t)c0 * N + r0 + 8] = __float2half(acc[mi][ni][2] * cscale);
      g_MT[(size_t)(c0 + 1) * N + r0 + 8] = __float2half(acc[mi][ni][3] * cscale);
    }
}

// =====================================================================
// copy_ctx: warp-per-row gather+convert (R13-proven). grid (8, 256).
// =====================================================================
__global__ void __launch_bounds__(256) copy_ctx(const float* __restrict__ ctx) {
  __shared__ int lr[32];
  const int b = blockIdx.y, slice = blockIdx.x;
  const int t = threadIdx.x, lane = t & 31, w = t >> 5;
  const int cnt = g_cnt[b], start = g_start[b];
  const int r0 = slice * 32;
  if (t < 32 && r0 + t < cnt) lr[t] = g_rowmap[start + r0 + t] - b * CL;
  __syncthreads();
  const int nrows = min(32, cnt - r0);
  for (int row = w; row < nrows; row += 8) {
    const float4* src = (const float4*)(ctx + ((size_t)b * CL + lr[row]) * CD);
    uint2* dst = (uint2*)(g_ctx_c + (size_t)(start + r0 + row) * CD);
#pragma unroll
    for (int j = 0; j < 6; j++) {
      float4 v = src[lane + j * 32];
      dst[lane + j * 32] = make_uint2(pack2h(v.x, v.y), pack2h(v.z, v.w));
    }
  }
}

// =====================================================================
// copy_cand: warp-per-row gather+convert with fused v' dot (R13-proven
// at 61% HBM; single cand read). grid (8, 256). Runs on a FORKED stream
// concurrent with copy_ctx + mm0 (depends only on maps).
// =====================================================================
__global__ void __launch_bounds__(256) copy_cand(const float* __restrict__ cand,
                                                 const float* __restrict__ WV) {
  __shared__ int sr[32];
  const int b = blockIdx.y, slice = blockIdx.x;
  const int t = threadIdx.x, lane = t & 31, w = t >> 5;
  const int cs = g_cnt_s[b];
  const int r0 = slice * 32;
  if (t < 32 && r0 + t < cs) sr[t] = g_colmap[b * 256 + r0 + t];
  __syncthreads();
  const int nrows = min(32, cs - r0);
  const float4* wv4 = (const float4*)WV;
  for (int row = w; row < nrows; row += 8) {
    const float4* src = (const float4*)(cand + ((size_t)b * CS + sr[row]) * CD);
    uint2* dst = (uint2*)(g_cand_c + ((size_t)b * 256 + r0 + row) * CD);
    float p = 0.f;
#pragma unroll
    for (int j = 0; j < 6; j++) {
      float4 v = src[lane + j * 32];
      float4 y = wv4[lane + j * 32];
      p += v.x * y.x + v.y * y.y + v.z * y.z + v.w * y.w;
      dst[lane + j * 32] = make_uint2(pack2h(v.x, v.y), pack2h(v.z, v.w));
    }
#pragma unroll
    for (int o = 16; o > 0; o >>= 1) p += __shfl_xor_sync(~0u, p, o);
    if (lane == 0) g_v[b * 256 + r0 + row] = p;
  }
}

// =====================================================================
// Unified 128x128xK=768 fp16 mainloop (proven R8 config): m16n8k16,
// ldmatrix b16 fragments, 3-stage cp.async, 8 warps 32x64 tiles,
// 2 CTAs/SM.
// MODE 0 (qgemm):  A = ctx_c rows, B = g_MT,    epilogue: store q'' fp16
// MODE 1 (agemm):  A = q_c rows,   B = cand_c,  epilogue: sigmoid*v -> x
// =====================================================================
template <int MODE>
__global__ void __launch_bounds__(256, 2) mm_main() {
  extern __shared__ char sm[];
  const int tid = threadIdx.x, lane = tid & 31, warp = tid >> 5;
  const int wm = warp >> 1, wn = warp & 1;
  const int grp = lane >> 2, qd = lane & 3;

  const char* Abase;
  const char* Bbase;
  int b = 0, mt = 0, nt = 0, cnt = 0, start = 0;
  if (MODE == 0) {
    int ptot = (g_total + 127) & ~127;
    if ((int)blockIdx.y * 128 >= ptot) return;
    Abase = (const char*)(g_ctx_c + (size_t)blockIdx.y * 128 * CD);
    Bbase = (const char*)(g_MT + (size_t)blockIdx.x * 128 * CD);
  } else {
    b = blockIdx.y; mt = blockIdx.x >> 1; nt = blockIdx.x & 1;
    cnt = g_cnt[b];
    int cs = g_cnt_s[b];
    if (mt * 128 >= cnt || nt * 128 >= cs) return;
    start = g_start[b];
    Abase = (const char*)(g_qc + (size_t)(start + mt * 128) * CD);
    Bbase = (const char*)(g_cand_c + ((size_t)b * 256 + nt * 128) * CD);
  }

  float* v_s = (float*)sm;          // [128]
  float* x_s = (float*)(sm + 512);  // [128]
  char* stg = sm + 1024;
  const uint32_t sb = smem_u32(stg);
  constexpr int RSTR = 144;          // 64 halves (128B) + 16B pad, conflict-free
  constexpr int ASZ = 128 * RSTR;    // 18432
  constexpr int STG = 2 * ASZ;       // 36864
  constexpr int KT = CD / 64;        // 12 k-tiles

  if (MODE == 1 && tid < 128) {
    x_s[tid] = 0.f;
    v_s[tid] = g_v[b * 256 + nt * 128 + tid];
  }

  // ldmatrix per-lane byte offsets (fp16 m16n8k16 canonical x4 pattern)
  const int l7 = lane & 7, lb3 = (lane >> 3) & 1, lb4 = lane >> 4;
  const uint32_t a_base0 = (uint32_t)((wm * 32 + l7 + lb3 * 8) * RSTR + lb4 * 16);
  const uint32_t a_base1 = a_base0 + 16 * RSTR;
  uint32_t b_base[4];
#pragma unroll
  for (int j = 0; j < 4; j++)
    b_base[j] = (uint32_t)((wn * 64 + j * 16 + l7 + lb4 * 8) * RSTR + lb3 * 16);

  float acc[2][8][4];
#pragma unroll
  for (int i = 0; i < 2; i++)
#pragma unroll
    for (int j = 0; j < 8; j++)
#pragma unroll
      for (int t = 0; t < 4; t++) acc[i][j][t] = 0.f;

  auto issue = [&](int kt) {
    if (kt < KT) {
      int s = kt - (kt / 3) * 3;
      uint32_t ab = sb + s * STG, bb = ab + ASZ;
#pragma unroll
      for (int i = 0; i < 4; i++) {
        int f = tid + i * 256, r = f >> 3, c = f & 7;
        cp16(ab + r * RSTR + c * 16, Abase + (size_t)r * 1536 + kt * 128 + c * 16);
        cp16(bb + r * RSTR + c * 16, Bbase + (size_t)r * 1536 + kt * 128 + c * 16);
      }
    }
    CP_COMMIT();
  };

  issue(0);
  issue(1);
  for (int kt = 0; kt < KT; ++kt) {
    CP_WAIT1();
    __syncthreads();
    issue(kt + 2);
    const int s = kt - (kt / 3) * 3;
    const uint32_t abp = sb + s * STG;
    const uint32_t bbp = abp + ASZ;
#pragma unroll
    for (int ks = 0; ks < 4; ks++) {
      const uint32_t ka = ks * 32;  // k16 = 32 bytes
      unsigned a0[4], a1[4];
      LDSM_X4(a0[0], a0[1], a0[2], a0[3], abp + a_base0 + ka);
      LDSM_X4(a1[0], a1[1], a1[2], a1[3], abp + a_base1 + ka);
#pragma unroll
      for (int j = 0; j < 4; j++) {
        unsigned bf0, bf1, bf2, bf3;
        LDSM_X4(bf0, bf1, bf2, bf3, bbp + b_base[j] + ka);
        mma16(acc[0][2 * j], a0, bf0, bf1);
        mma16(acc[1][2 * j], a1, bf0, bf1);
        mma16(acc[0][2 * j + 1], a0, bf2, bf3);
        mma16(acc[1][2 * j + 1], a1, bf2, bf3);
      }
    }
  }

  if (MODE == 0) {
    const int i0 = blockIdx.y * 128, bn = blockIdx.x;
#pragma unroll
    for (int mi = 0; mi < 2; mi++)
#pragma unroll
      for (int ni = 0; ni < 8; ni++) {
        int r = wm * 32 + mi * 16 + grp;
        int c = bn * 128 + wn * 64 + ni * 8 + qd * 2;
        size_t o = (size_t)(i0 + r) * CD + c;
        *(uint32_t*)(g_qc + o) = pack2h(acc[mi][ni][0], acc[mi][ni][1]);
        o += (size_t)8 * CD;
        *(uint32_t*)(g_qc + o) = pack2h(acc[mi][ni][2], acc[mi][ni][3]);
      }
  } else {
    float xp[2][2] = {{0.f, 0.f}, {0.f, 0.f}};
#pragma unroll
    for (int mi = 0; mi < 2; mi++)
#pragma unroll
      for (int ni = 0; ni < 8; ni++) {
        int c0 = wn * 64 + ni * 8 + qd * 2;
        float va = v_s[c0], vb = v_s[c0 + 1];
        xp[mi][0] += va / (1.f + __expf(-acc[mi][ni][0])) + vb / (1.f + __expf(-acc[mi][ni][1]));
        xp[mi][1] += va / (1.f + __expf(-acc[mi][ni][2])) + vb / (1.f + __expf(-acc[mi][ni][3]));
      }
#pragma unroll
    for (int mi = 0; mi < 2; mi++)
#pragma unroll
      for (int rs = 0; rs < 2; rs++) {
        float v = xp[mi][rs];
        v += __shfl_xor_sync(0xffffffffu, v, 1);
        v += __shfl_xor_sync(0xffffffffu, v, 2);
        if (qd == 0) atomicAdd(&x_s[wm * 32 + mi * 16 + rs * 8 + grp], v);
      }
    __syncthreads();
    if (tid < 128 && mt * 128 + tid < cnt)
      atomicAdd(&g_x[g_rowmap[start + mt * 128 + tid]], x_s[tid]);
  }
}

// =====================================================================
// Head: y[b,:] = (x_b @ W1 + b1) @ W2 + b2.
// =====================================================================
__global__ void head_kernel(const float* __restrict__ W1, const float* __restrict__ b1,
                            const float* __restrict__ W2, const float* __restrict__ b2,
                            float* __restrict__ out) {
  __shared__ float xs[CL];
  __shared__ float hs[CH];
  int b = blockIdx.x, tid = threadIdx.x;
  xs[tid] = g_x[b * CL + tid];
  xs[tid + 128] = g_x[b * CL + tid + 128];
  __syncthreads();
  float h = b1[tid];
  for (int l = 0; l < CL; l++) h += xs[l] * W1[l * CH + tid];
  hs[tid] = h;
  __syncthreads();
  if (tid < 5) {
    float y = b2[tid];
    for (int k = 0; k < CH; k++) y += hs[k] * W2[k * 5 + tid];
    out[b * 5 + tid] = y;
  }
}

extern "C" void kernel_launch(void* const* d_in, const int* in_sizes, int n_in,
                              void* d_out, int out_size) {
  const float* ctx = (const float*)d_in[0];
  const float* cand = (const float*)d_in[1];
  const int* ctx_mask = (const int*)d_in[2];
  const int* cand_mask = (const int*)d_in[3];
  const float* WK = (const float*)d_in[4];
  const float* WQ = (const float*)d_in[5];
  const float* WV = (const float*)d_in[6];
  const float* W1 = (const float*)d_in[7];
  const float* b1 = (const float*)d_in[8];
  const float* W2 = (const float*)d_in[9];
  const float* b2 = (const float*)d_in[10];
  float* out = (float*)d_out;
  (void)in_sizes; (void)n_in; (void)out_size;

  constexpr int GEMM_SMEM = (2 * 128 * 36 + 2 * 32 * 132) * 4;  // 70656
  constexpr int MM_SMEM = 1024 + 3 * (2 * 128 * 144);           // 111616

  cudaFuncSetAttribute(k0_kernel, cudaFuncAttributeMaxDynamicSharedMemorySize, GEMM_SMEM);
  cudaFuncSetAttribute(mm_main<0>, cudaFuncAttributeMaxDynamicSharedMemorySize, MM_SMEM);
  cudaFuncSetAttribute(mm_main<1>, cudaFuncAttributeMaxDynamicSharedMemorySize, MM_SMEM);

  // One-time side streams + events for graph fork-join (created once on the
  // uncaptured correctness call; reused identically every call). Falls back
  // to sequential legacy-stream launches if creation fails.
  static cudaStream_t s2 = nullptr, s3 = nullptr;
  static cudaEvent_t evM = nullptr, evB = nullptr, evK = nullptr, ev0 = nullptr;
  static int init_ok = -1;
  if (init_ok < 0) {
    init_ok = 1;
    if (cudaStreamCreateWithFlags(&s2, cudaStreamNonBlocking) != cudaSuccess) init_ok = 0;
    if (init_ok && cudaStreamCreateWithFlags(&s3, cudaStreamNonBlocking) != cudaSuccess) init_ok = 0;
    if (init_ok && cudaEventCreateWithFlags(&evM, cudaEventDisableTiming) != cudaSuccess) init_ok = 0;
    if (init_ok && cudaEventCreateWithFlags(&evB, cudaEventDisableTiming) != cudaSuccess) init_ok = 0;
    if (init_ok && cudaEventCreateWithFlags(&evK, cudaEventDisableTiming) != cudaSuccess) init_ok = 0;
    if (init_ok && cudaEventCreateWithFlags(&ev0, cudaEventDisableTiming) != cudaSuccess) init_ok = 0;
  }

  float scale = 1.0f / sqrtf((float)CD);

  if (init_ok) {
    // s3: K0 depends only on inputs -- launch immediately, fully parallel
    cudaEventRecord(ev0, 0);            // capture-graph root ordering
    cudaStreamWaitEvent(s3, ev0, 0);
    k0_kernel<<<36, 256, GEMM_SMEM, s3>>>(WQ, WK, scale);
    cudaEventRecord(evK, s3);
    // main: scan -> maps
    scan1<<<1, 1024>>>(ctx_mask, cand_mask);
    maps_kernel<<<256, 256>>>(ctx_mask, cand_mask);
    // s2: copy_cand after maps (joined before mm1 -> hidden under mm0)
    cudaEventRecord(evM, 0);
    cudaStreamWaitEvent(s2, evM, 0);
    copy_cand<<<dim3(8, CB), 256, 0, s2>>>(cand, WV);
    cudaEventRecord(evB, s2);
    // main: ctx copy, then join K0 before mm0
    copy_ctx<<<dim3(8, CB), 256>>>(ctx);
    cudaStreamWaitEvent(0, evK, 0);
    mm_main<0><<<dim3(CD / 128, (CB * CL) / 128), 256, MM_SMEM>>>();
    cudaStreamWaitEvent(0, evB, 0);
  } else {
    scan1<<<1, 1024>>>(ctx_mask, cand_mask);
    maps_kernel<<<256, 256>>>(ctx_mask, cand_mask);
    k0_kernel<<<36, 256, GEMM_SMEM>>>(WQ, WK, scale);
    copy_ctx<<<dim3(8, CB), 256>>>(ctx);
    copy_cand<<<dim3(8, CB), 256>>>(cand, WV);
    mm_main<0><<<dim3(CD / 128, (CB * CL) / 128), 256, MM_SMEM>>>();
  }

  // fused logits -> sigmoid -> x (proven config, full tiling)
  mm_main<1><<<dim3(4, CB), 256, MM_SMEM>>>();
  // head MLP -> y
  head_kernel<<<CB, CH>>>(W1, b1, W2, b2, out);
}